// round 12
// baseline (speedup 1.0000x reference)
#include <cuda_runtime.h>
#include <cstdint>
#include <cstddef>

#define BB 4
#define NN 8192
#define SS 2048
#define KK 32
#define DD 64

// group indices scratch: [B*S, K]
__device__ int g_grp[BB * SS * KK];
// h2 activations scratch: [group][chunk(32)][k(32)] float4 = 134MB
__device__ float4 g_h2[(size_t)BB * SS * 32 * 32];

// ---------------- packed f32x2 helpers (per-lane IEEE == scalar) ----------
__device__ __forceinline__ unsigned long long pk2(float lo, float hi) {
    unsigned long long r;
    asm("mov.b64 %0, {%1, %2};" : "=l"(r) : "f"(lo), "f"(hi));
    return r;
}
__device__ __forceinline__ void upk2(unsigned long long v, float& lo, float& hi) {
    asm("mov.b64 {%0, %1}, %2;" : "=f"(lo), "=f"(hi) : "l"(v));
}
__device__ __forceinline__ unsigned long long add2(unsigned long long a, unsigned long long b) {
    unsigned long long r;
    asm("add.rn.f32x2 %0, %1, %2;" : "=l"(r) : "l"(a), "l"(b));
    return r;
}
__device__ __forceinline__ unsigned long long mul2(unsigned long long a, unsigned long long b) {
    unsigned long long r;
    asm("mul.rn.f32x2 %0, %1, %2;" : "=l"(r) : "l"(a), "l"(b));
    return r;
}
__device__ __forceinline__ void fma2(unsigned long long& d, unsigned long long a, unsigned long long b) {
    asm("fma.rn.f32x2 %0, %1, %2, %0;" : "+l"(d) : "l"(a), "l"(b));
}

// ------------------------------------------------------------------
// Kernel 1: farthest point sampling (unchanged from R9, verified).
// ------------------------------------------------------------------
__global__ __launch_bounds__(1024, 1)
void fps_kernel(const float* __restrict__ xyz, float* __restrict__ newxyz)
{
    extern __shared__ float4 sxyz[];           // 8192 * 16B = 128KB
    __shared__ unsigned int sd[2][32];
    __shared__ int          si[2][32];

    const int b    = blockIdx.x;
    const int tid  = threadIdx.x;
    const int lane = tid & 31;
    const float* xb = xyz + (size_t)b * NN * 3;

    unsigned long long pxp[4], pyp[4], pzp[4];
    float dist[8];
#pragma unroll
    for (int j = 0; j < 4; j++) {
        int p0 = tid * 8 + 2 * j;
        float x0 = xb[p0 * 3 + 0], y0 = xb[p0 * 3 + 1], z0 = xb[p0 * 3 + 2];
        float x1 = xb[p0 * 3 + 3], y1 = xb[p0 * 3 + 4], z1 = xb[p0 * 3 + 5];
        pxp[j] = pk2(x0, x1); pyp[j] = pk2(y0, y1); pzp[j] = pk2(z0, z1);
        dist[2 * j] = 1e10f; dist[2 * j + 1] = 1e10f;
        sxyz[p0]     = make_float4(x0, y0, z0, 0.0f);
        sxyz[p0 + 1] = make_float4(x1, y1, z1, 0.0f);
    }
    __syncthreads();

    int cur = 0;
    for (int s = 0; s < SS; s++) {
        float4 c4 = sxyz[cur];                 // LDS.128 broadcast
        if (tid == 0) {
            float* o = newxyz + ((size_t)b * SS + s) * 3;
            o[0] = c4.x; o[1] = c4.y; o[2] = c4.z;
        }
        unsigned long long cx2 = pk2(-c4.x, -c4.x);
        unsigned long long cy2 = pk2(-c4.y, -c4.y);
        unsigned long long cz2 = pk2(-c4.z, -c4.z);
        float bv = -1.0f;
#pragma unroll
        for (int j = 0; j < 4; j++) {
            unsigned long long dx = add2(pxp[j], cx2);
            unsigned long long dy = add2(pyp[j], cy2);
            unsigned long long dz = add2(pzp[j], cz2);
            unsigned long long dd = add2(add2(mul2(dx, dx), mul2(dy, dy)),
                                         mul2(dz, dz));
            float dl, dh; upk2(dd, dl, dh);
            float n0 = fminf(dist[2 * j],     dl);
            float n1 = fminf(dist[2 * j + 1], dh);
            dist[2 * j]     = n0;
            dist[2 * j + 1] = n1;
            bv = fmaxf(bv, fmaxf(n0, n1));
        }
        int bi = 0;
#pragma unroll
        for (int j = 7; j >= 0; j--) if (dist[j] == bv) bi = j;

        unsigned db = __float_as_uint(bv);     // dist>=0: uint order == float order
        unsigned wm = __reduce_max_sync(0xffffffffu, db);
        unsigned bl = __ballot_sync(0xffffffffu, db == wm);
        int src  = __ffs(bl) - 1;              // smallest lane == smallest index
        int widx = __shfl_sync(0xffffffffu, tid * 8 + bi, src);

        int par = s & 1;
        if (lane == 0) { sd[par][tid >> 5] = wm; si[par][tid >> 5] = widx; }
        __syncthreads();
        unsigned vd = sd[par][lane];
        int      vi = si[par][lane];
        unsigned m2 = __reduce_max_sync(0xffffffffu, vd);
        unsigned b2 = __ballot_sync(0xffffffffu, vd == m2);
        int s2 = __ffs(b2) - 1;                // smallest warp == smallest index
        cur = __shfl_sync(0xffffffffu, vi, s2);
    }
}

// ------------------------------------------------------------------
// Kernel 2: ball query (unchanged from R9, verified).
// ------------------------------------------------------------------
__global__ __launch_bounds__(256)
void ballq_kernel(const float* __restrict__ xyz,
                  const float* __restrict__ newxyz)
{
    const int w    = (blockIdx.x * blockDim.x + threadIdx.x) >> 5;
    const int lane = threadIdx.x & 31;
    const int b = w >> 11;                      // w / 2048
    const float* xb = xyz + (size_t)b * NN * 3;
    const float* nw = newxyz + (size_t)w * 3;

    float nx = nw[0], ny = nw[1], nz = nw[2];
    float nsq = __fadd_rn(__fadd_rn(__fmul_rn(nx, nx), __fmul_rn(ny, ny)),
                          __fmul_rn(nz, nz));
    int cnt = 0;
    int first = 0;
    int* g = g_grp + (size_t)w * KK;

    for (int base = 0; base < NN; base += 32) {
        int p = base + lane;
        float x = xb[p * 3 + 0];
        float y = xb[p * 3 + 1];
        float z = xb[p * 3 + 2];
        float xsq = __fadd_rn(__fadd_rn(__fmul_rn(x, x), __fmul_rn(y, y)),
                              __fmul_rn(z, z));
        float dot = __fmaf_rn(nz, z, __fmaf_rn(ny, y, __fmul_rn(nx, x)));
        float sq  = __fsub_rn(__fadd_rn(nsq, xsq), __fmul_rn(2.0f, dot));
        bool hit  = !(sq > 0.04f);
        unsigned m = __ballot_sync(0xffffffffu, hit);
        if (cnt == 0 && m) first = base + __ffs(m) - 1;
        int pos = cnt + __popc(m & ((1u << lane) - 1u));
        if (hit && pos < KK) g[pos] = p;
        cnt += __popc(m);
        if (cnt >= KK) break;
    }
    if (cnt < KK) {
        for (int k = cnt + lane; k < KK; k += 32) g[k] = first;
    }
}

// ------------------------------------------------------------------
// Kernel 3A: gather + layers 1,2 (FFMA2 channel pairs, bit-exact),
// h2 streamed to global scratch (group stride 1024 float4).
//   sW1p [0,4352) sW2p [4352,12544) b1 [12544,12608) b2 [12608,12736)
// ------------------------------------------------------------------
#define A_W1 0
#define A_W2 4352
#define A_B1 12544
#define A_B2 12608
#define A_FLOATS 12736

__global__ __launch_bounds__(256, 1)
void mlp12_kernel(const float* __restrict__ xyz,
                  const float* __restrict__ features,
                  const float* __restrict__ W1, const float* __restrict__ b1,
                  const float* __restrict__ W2, const float* __restrict__ b2,
                  const float* __restrict__ newxyz)
{
    extern __shared__ float sm[];
    const int tid  = threadIdx.x;
    const int lane = tid & 31;

    for (int t = tid; t < 64 * 68; t += 256) {
        int f = t >> 2, c = t & 3;
        int op = f / 34, ip = f - op * 34;
        int ch = 2 * op + (c & 1);
        int i  = 2 * ip + (c >> 1);
        sm[A_W1 + t] = (i < 67) ? W1[ch * 67 + i] : 0.0f;
    }
    for (int t = tid; t < 128 * 64; t += 256) {
        int f = t >> 2, c = t & 3;
        int op = f >> 5, ip = f & 31;
        int ch = 2 * op + (c & 1);
        int i  = 2 * ip + (c >> 1);
        sm[A_W2 + t] = W2[ch * 64 + i];
    }
    if (tid < 64)  sm[A_B1 + tid] = b1[tid];
    if (tid < 128) sm[A_B2 + tid] = b2[tid];
    __syncthreads();

    const int g = blockIdx.x * 8 + (tid >> 5);
    const int b = g >> 11;
    const int gi = g_grp[(size_t)g * KK + lane];

    float h0[68];
    {
        const float* ctr  = newxyz + (size_t)g * 3;
        const float* pxyz = xyz + ((size_t)b * NN + gi) * 3;
        h0[0] = pxyz[0] - ctr[0];
        h0[1] = pxyz[1] - ctr[1];
        h0[2] = pxyz[2] - ctr[2];
        const float4* fr = (const float4*)(features + ((size_t)b * NN + gi) * DD);
#pragma unroll
        for (int t = 0; t < 16; t++) {
            float4 v = fr[t];
            h0[3 + 4 * t] = v.x; h0[4 + 4 * t] = v.y;
            h0[5 + 4 * t] = v.z; h0[6 + 4 * t] = v.w;
        }
        h0[67] = 0.0f;
    }

    const ulonglong2* w1p = (const ulonglong2*)(sm + A_W1);
    const ulonglong2* w2p = (const ulonglong2*)(sm + A_W2);
    const unsigned long long* bb1 = (const unsigned long long*)(sm + A_B1);
    const unsigned long long* bb2 = (const unsigned long long*)(sm + A_B2);

    // ---- layer 1: 67(+pad) -> 64 ----
    float h1[64];
    {
        unsigned long long acc[32];
#pragma unroll
        for (int op = 0; op < 32; op++) acc[op] = bb1[op];
#pragma unroll
        for (int ip = 0; ip < 34; ip++) {
            unsigned long long hd0 = pk2(h0[2 * ip],     h0[2 * ip]);
            unsigned long long hd1 = pk2(h0[2 * ip + 1], h0[2 * ip + 1]);
#pragma unroll
            for (int op = 0; op < 32; op++) {
                ulonglong2 w = w1p[op * 34 + ip];
                fma2(acc[op], w.x, hd0);
                fma2(acc[op], w.y, hd1);
            }
        }
#pragma unroll
        for (int op = 0; op < 32; op++) {
            float v0, v1; upk2(acc[op], v0, v1);
            h1[2 * op]     = fmaxf(v0, 0.0f);
            h1[2 * op + 1] = fmaxf(v1, 0.0f);
        }
    }

    // ---- layer 2: 64 -> 128, streamed to scratch per 64-ch chunk ----
    float4* h2o = g_h2 + (size_t)g * 1024;     // 32 chunks x 32 lanes
#pragma unroll
    for (int oc = 0; oc < 2; oc++) {
        unsigned long long acc[32];
#pragma unroll
        for (int opl = 0; opl < 32; opl++) acc[opl] = bb2[oc * 32 + opl];
#pragma unroll
        for (int ip = 0; ip < 32; ip++) {
            unsigned long long hd0 = pk2(h1[2 * ip],     h1[2 * ip]);
            unsigned long long hd1 = pk2(h1[2 * ip + 1], h1[2 * ip + 1]);
#pragma unroll
            for (int opl = 0; opl < 32; opl++) {
                ulonglong2 w = w2p[(oc * 32 + opl) * 32 + ip];
                fma2(acc[opl], w.x, hd0);
                fma2(acc[opl], w.y, hd1);
            }
        }
        // relu + pack to float4, coalesced store ([chunk][k] layout)
#pragma unroll
        for (int t = 0; t < 16; t++) {
            float v0, v1, v2, v3;
            upk2(acc[2 * t],     v0, v1);
            upk2(acc[2 * t + 1], v2, v3);
            float4 o;
            o.x = fmaxf(v0, 0.0f); o.y = fmaxf(v1, 0.0f);
            o.z = fmaxf(v2, 0.0f); o.w = fmaxf(v3, 0.0f);
            h2o[(oc * 16 + t) * 32 + lane] = o;
        }
    }
}

// ------------------------------------------------------------------
// Kernel 3B: layer 3 (128->256) + max-pool over K. h2 from scratch
// (group stride 1024 float4). W3 staged interleaved in shared.
//   sW3p [0,32768) b3 [32768,33024)
// ------------------------------------------------------------------
#define B_W3 0
#define B_B3 32768
#define B_FLOATS 33024

__global__ __launch_bounds__(256, 1)
void mlp3_kernel(const float* __restrict__ W3, const float* __restrict__ b3,
                 float* __restrict__ feats_out)
{
    extern __shared__ float sm[];
    const int tid  = threadIdx.x;
    const int lane = tid & 31;

    for (int t = tid; t < 256 * 128; t += 256) {
        int f = t >> 2, c = t & 3;
        int op = f >> 6, ip = f & 63;
        int ch = 2 * op + (c & 1);
        int i  = 2 * ip + (c >> 1);
        sm[B_W3 + t] = W3[ch * 128 + i];
    }
    sm[B_B3 + tid] = b3[tid & 255];
    __syncthreads();

    const int g = blockIdx.x * 8 + (tid >> 5);

    // coalesced load of this lane's h2 (128 floats)
    float h2[128];
    {
        const float4* h2i = g_h2 + (size_t)g * 1024;
#pragma unroll
        for (int t = 0; t < 32; t++) {
            float4 v = h2i[t * 32 + lane];
            h2[4 * t]     = v.x; h2[4 * t + 1] = v.y;
            h2[4 * t + 2] = v.z; h2[4 * t + 3] = v.w;
        }
    }

    const ulonglong2* w3p = (const ulonglong2*)(sm + B_W3);
    const unsigned long long* bb3 = (const unsigned long long*)(sm + B_B3);

    float maxv[8];
#pragma unroll
    for (int cc = 0; cc < 8; cc++) {
        unsigned long long acc[16];
#pragma unroll
        for (int opl = 0; opl < 16; opl++) acc[opl] = bb3[cc * 16 + opl];
#pragma unroll
        for (int ip = 0; ip < 64; ip++) {
            unsigned long long hd0 = pk2(h2[2 * ip],     h2[2 * ip]);
            unsigned long long hd1 = pk2(h2[2 * ip + 1], h2[2 * ip + 1]);
#pragma unroll
            for (int opl = 0; opl < 16; opl++) {
                ulonglong2 w = w3p[(cc * 16 + opl) * 64 + ip];
                fma2(acc[opl], w.x, hd0);
                fma2(acc[opl], w.y, hd1);
            }
        }
#pragma unroll
        for (int opl = 0; opl < 16; opl++) {
            float v0, v1; upk2(acc[opl], v0, v1);
            v0 = fmaxf(v0, 0.0f);
            v1 = fmaxf(v1, 0.0f);
#pragma unroll
            for (int off = 16; off; off >>= 1) {
                v0 = fmaxf(v0, __shfl_xor_sync(0xffffffffu, v0, off));
                v1 = fmaxf(v1, __shfl_xor_sync(0xffffffffu, v1, off));
            }
            if (lane == 2 * opl)     maxv[cc] = v0;
            if (lane == 2 * opl + 1) maxv[cc] = v1;
        }
    }
#pragma unroll
    for (int cc = 0; cc < 8; cc++)
        feats_out[(size_t)g * 256 + cc * 32 + lane] = maxv[cc];
}

// ------------------------------------------------------------------
extern "C" void kernel_launch(void* const* d_in, const int* in_sizes, int n_in,
                              void* d_out, int out_size)
{
    const float* xyz      = (const float*)d_in[0];
    const float* features = (const float*)d_in[1];
    const float* W1 = (const float*)d_in[2];
    const float* b1 = (const float*)d_in[3];
    const float* W2 = (const float*)d_in[4];
    const float* b2 = (const float*)d_in[5];
    const float* W3 = (const float*)d_in[6];
    const float* b3 = (const float*)d_in[7];

    float* out    = (float*)d_out;
    float* newxyz = out;                         // [B,S,3] = 24576 floats
    float* feats  = out + (size_t)BB * SS * 3;   // [B,S,256]

    cudaFuncSetAttribute(fps_kernel, cudaFuncAttributeMaxDynamicSharedMemorySize,
                         NN * (int)sizeof(float4));
    cudaFuncSetAttribute(mlp12_kernel, cudaFuncAttributeMaxDynamicSharedMemorySize,
                         A_FLOATS * (int)sizeof(float));
    cudaFuncSetAttribute(mlp3_kernel, cudaFuncAttributeMaxDynamicSharedMemorySize,
                         B_FLOATS * (int)sizeof(float));

    fps_kernel<<<BB, 1024, NN * sizeof(float4)>>>(xyz, newxyz);
    ballq_kernel<<<(BB * SS * 32) / 256, 256>>>(xyz, newxyz);
    mlp12_kernel<<<(BB * SS) / 8, 256, A_FLOATS * sizeof(float)>>>(
        xyz, features, W1, b1, W2, b2, newxyz);
    mlp3_kernel<<<(BB * SS) / 8, 256, B_FLOATS * sizeof(float)>>>(
        W3, b3, feats);
}

// round 13
// speedup vs baseline: 1.2923x; 1.2923x over previous
#include <cuda_runtime.h>
#include <cstdint>
#include <cstddef>

#define BB 4
#define NN 8192
#define SS 2048
#define KK 32
#define DD 64

// group indices scratch: [B*S, K]
__device__ int g_grp[BB * SS * KK];
// h2 activations scratch: [group][chunk(32)][k(32)] float4 = 134MB
// float4 at chunk c holds input-channels ip = 4c..4c+3 for neighbor k=lane.
__device__ float4 g_h2[(size_t)BB * SS * 32 * 32];

// ---------------- packed f32x2 helpers (per-lane IEEE == scalar) ----------
__device__ __forceinline__ unsigned long long pk2(float lo, float hi) {
    unsigned long long r;
    asm("mov.b64 %0, {%1, %2};" : "=l"(r) : "f"(lo), "f"(hi));
    return r;
}
__device__ __forceinline__ void upk2(unsigned long long v, float& lo, float& hi) {
    asm("mov.b64 {%0, %1}, %2;" : "=f"(lo), "=f"(hi) : "l"(v));
}
__device__ __forceinline__ unsigned long long add2(unsigned long long a, unsigned long long b) {
    unsigned long long r;
    asm("add.rn.f32x2 %0, %1, %2;" : "=l"(r) : "l"(a), "l"(b));
    return r;
}
__device__ __forceinline__ unsigned long long mul2(unsigned long long a, unsigned long long b) {
    unsigned long long r;
    asm("mul.rn.f32x2 %0, %1, %2;" : "=l"(r) : "l"(a), "l"(b));
    return r;
}
__device__ __forceinline__ void fma2(unsigned long long& d, unsigned long long a, unsigned long long b) {
    asm("fma.rn.f32x2 %0, %1, %2, %0;" : "+l"(d) : "l"(a), "l"(b));
}

// TF32 rounding (round-to-nearest-away, as cuBLAS uses for tf32 operands).
__device__ __forceinline__ float tf32r(float x)
{
    float r;
    asm("cvt.rna.tf32.f32 %0, %1;" : "=f"(r) : "f"(x));
    return r;
}

// m16n8k8 tf32 MMA, D = A*B + D (f32 accumulate).
__device__ __forceinline__ void mma_tf32(float& d0, float& d1, float& d2, float& d3,
                                         uint32_t a0, uint32_t a1, uint32_t a2, uint32_t a3,
                                         uint32_t b0, uint32_t b1)
{
    asm("mma.sync.aligned.m16n8k8.row.col.f32.tf32.tf32.f32 "
        "{%0,%1,%2,%3},{%4,%5,%6,%7},{%8,%9},{%0,%1,%2,%3};"
        : "+f"(d0), "+f"(d1), "+f"(d2), "+f"(d3)
        : "r"(a0), "r"(a1), "r"(a2), "r"(a3), "r"(b0), "r"(b1));
}

// ------------------------------------------------------------------
// Kernel 1: farthest point sampling (unchanged, verified bit-exact).
// ------------------------------------------------------------------
__global__ __launch_bounds__(1024, 1)
void fps_kernel(const float* __restrict__ xyz, float* __restrict__ newxyz)
{
    extern __shared__ float4 sxyz[];           // 8192 * 16B = 128KB
    __shared__ unsigned int sd[2][32];
    __shared__ int          si[2][32];

    const int b    = blockIdx.x;
    const int tid  = threadIdx.x;
    const int lane = tid & 31;
    const float* xb = xyz + (size_t)b * NN * 3;

    unsigned long long pxp[4], pyp[4], pzp[4];
    float dist[8];
#pragma unroll
    for (int j = 0; j < 4; j++) {
        int p0 = tid * 8 + 2 * j;
        float x0 = xb[p0 * 3 + 0], y0 = xb[p0 * 3 + 1], z0 = xb[p0 * 3 + 2];
        float x1 = xb[p0 * 3 + 3], y1 = xb[p0 * 3 + 4], z1 = xb[p0 * 3 + 5];
        pxp[j] = pk2(x0, x1); pyp[j] = pk2(y0, y1); pzp[j] = pk2(z0, z1);
        dist[2 * j] = 1e10f; dist[2 * j + 1] = 1e10f;
        sxyz[p0]     = make_float4(x0, y0, z0, 0.0f);
        sxyz[p0 + 1] = make_float4(x1, y1, z1, 0.0f);
    }
    __syncthreads();

    int cur = 0;
    for (int s = 0; s < SS; s++) {
        float4 c4 = sxyz[cur];                 // LDS.128 broadcast
        if (tid == 0) {
            float* o = newxyz + ((size_t)b * SS + s) * 3;
            o[0] = c4.x; o[1] = c4.y; o[2] = c4.z;
        }
        unsigned long long cx2 = pk2(-c4.x, -c4.x);
        unsigned long long cy2 = pk2(-c4.y, -c4.y);
        unsigned long long cz2 = pk2(-c4.z, -c4.z);
        float bv = -1.0f;
#pragma unroll
        for (int j = 0; j < 4; j++) {
            unsigned long long dx = add2(pxp[j], cx2);
            unsigned long long dy = add2(pyp[j], cy2);
            unsigned long long dz = add2(pzp[j], cz2);
            unsigned long long dd = add2(add2(mul2(dx, dx), mul2(dy, dy)),
                                         mul2(dz, dz));
            float dl, dh; upk2(dd, dl, dh);
            float n0 = fminf(dist[2 * j],     dl);
            float n1 = fminf(dist[2 * j + 1], dh);
            dist[2 * j]     = n0;
            dist[2 * j + 1] = n1;
            bv = fmaxf(bv, fmaxf(n0, n1));
        }
        int bi = 0;
#pragma unroll
        for (int j = 7; j >= 0; j--) if (dist[j] == bv) bi = j;

        unsigned db = __float_as_uint(bv);     // dist>=0: uint order == float order
        unsigned wm = __reduce_max_sync(0xffffffffu, db);
        unsigned bl = __ballot_sync(0xffffffffu, db == wm);
        int src  = __ffs(bl) - 1;              // smallest lane == smallest index
        int widx = __shfl_sync(0xffffffffu, tid * 8 + bi, src);

        int par = s & 1;
        if (lane == 0) { sd[par][tid >> 5] = wm; si[par][tid >> 5] = widx; }
        __syncthreads();
        unsigned vd = sd[par][lane];
        int      vi = si[par][lane];
        unsigned m2 = __reduce_max_sync(0xffffffffu, vd);
        unsigned b2 = __ballot_sync(0xffffffffu, vd == m2);
        int s2 = __ffs(b2) - 1;                // smallest warp == smallest index
        cur = __shfl_sync(0xffffffffu, vi, s2);
    }
}

// ------------------------------------------------------------------
// Kernel 2: ball query (unchanged, verified bit-exact).
// ------------------------------------------------------------------
__global__ __launch_bounds__(256)
void ballq_kernel(const float* __restrict__ xyz,
                  const float* __restrict__ newxyz)
{
    const int w    = (blockIdx.x * blockDim.x + threadIdx.x) >> 5;
    const int lane = threadIdx.x & 31;
    const int b = w >> 11;                      // w / 2048
    const float* xb = xyz + (size_t)b * NN * 3;
    const float* nw = newxyz + (size_t)w * 3;

    float nx = nw[0], ny = nw[1], nz = nw[2];
    float nsq = __fadd_rn(__fadd_rn(__fmul_rn(nx, nx), __fmul_rn(ny, ny)),
                          __fmul_rn(nz, nz));
    int cnt = 0;
    int first = 0;
    int* g = g_grp + (size_t)w * KK;

    for (int base = 0; base < NN; base += 32) {
        int p = base + lane;
        float x = xb[p * 3 + 0];
        float y = xb[p * 3 + 1];
        float z = xb[p * 3 + 2];
        float xsq = __fadd_rn(__fadd_rn(__fmul_rn(x, x), __fmul_rn(y, y)),
                              __fmul_rn(z, z));
        float dot = __fmaf_rn(nz, z, __fmaf_rn(ny, y, __fmul_rn(nx, x)));
        float sq  = __fsub_rn(__fadd_rn(nsq, xsq), __fmul_rn(2.0f, dot));
        bool hit  = !(sq > 0.04f);
        unsigned m = __ballot_sync(0xffffffffu, hit);
        if (cnt == 0 && m) first = base + __ffs(m) - 1;
        int pos = cnt + __popc(m & ((1u << lane) - 1u));
        if (hit && pos < KK) g[pos] = p;
        cnt += __popc(m);
        if (cnt >= KK) break;
    }
    if (cnt < KK) {
        for (int k = cnt + lane; k < KK; k += 32) g[k] = first;
    }
}

// ------------------------------------------------------------------
// Kernel 3A: gather + layers 1,2 (FFMA2, bit-exact) -> g_h2.
// (unchanged from R12, verified)
// ------------------------------------------------------------------
#define A_W1 0
#define A_W2 4352
#define A_B1 12544
#define A_B2 12608
#define A_FLOATS 12736

__global__ __launch_bounds__(256, 1)
void mlp12_kernel(const float* __restrict__ xyz,
                  const float* __restrict__ features,
                  const float* __restrict__ W1, const float* __restrict__ b1,
                  const float* __restrict__ W2, const float* __restrict__ b2,
                  const float* __restrict__ newxyz)
{
    extern __shared__ float sm[];
    const int tid  = threadIdx.x;
    const int lane = tid & 31;

    for (int t = tid; t < 64 * 68; t += 256) {
        int f = t >> 2, c = t & 3;
        int op = f / 34, ip = f - op * 34;
        int ch = 2 * op + (c & 1);
        int i  = 2 * ip + (c >> 1);
        sm[A_W1 + t] = (i < 67) ? W1[ch * 67 + i] : 0.0f;
    }
    for (int t = tid; t < 128 * 64; t += 256) {
        int f = t >> 2, c = t & 3;
        int op = f >> 5, ip = f & 31;
        int ch = 2 * op + (c & 1);
        int i  = 2 * ip + (c >> 1);
        sm[A_W2 + t] = W2[ch * 64 + i];
    }
    if (tid < 64)  sm[A_B1 + tid] = b1[tid];
    if (tid < 128) sm[A_B2 + tid] = b2[tid];
    __syncthreads();

    const int g = blockIdx.x * 8 + (tid >> 5);
    const int b = g >> 11;
    const int gi = g_grp[(size_t)g * KK + lane];

    float h0[68];
    {
        const float* ctr  = newxyz + (size_t)g * 3;
        const float* pxyz = xyz + ((size_t)b * NN + gi) * 3;
        h0[0] = pxyz[0] - ctr[0];
        h0[1] = pxyz[1] - ctr[1];
        h0[2] = pxyz[2] - ctr[2];
        const float4* fr = (const float4*)(features + ((size_t)b * NN + gi) * DD);
#pragma unroll
        for (int t = 0; t < 16; t++) {
            float4 v = fr[t];
            h0[3 + 4 * t] = v.x; h0[4 + 4 * t] = v.y;
            h0[5 + 4 * t] = v.z; h0[6 + 4 * t] = v.w;
        }
        h0[67] = 0.0f;
    }

    const ulonglong2* w1p = (const ulonglong2*)(sm + A_W1);
    const ulonglong2* w2p = (const ulonglong2*)(sm + A_W2);
    const unsigned long long* bb1 = (const unsigned long long*)(sm + A_B1);
    const unsigned long long* bb2 = (const unsigned long long*)(sm + A_B2);

    // ---- layer 1: 67(+pad) -> 64 ----
    float h1[64];
    {
        unsigned long long acc[32];
#pragma unroll
        for (int op = 0; op < 32; op++) acc[op] = bb1[op];
#pragma unroll
        for (int ip = 0; ip < 34; ip++) {
            unsigned long long hd0 = pk2(h0[2 * ip],     h0[2 * ip]);
            unsigned long long hd1 = pk2(h0[2 * ip + 1], h0[2 * ip + 1]);
#pragma unroll
            for (int op = 0; op < 32; op++) {
                ulonglong2 w = w1p[op * 34 + ip];
                fma2(acc[op], w.x, hd0);
                fma2(acc[op], w.y, hd1);
            }
        }
#pragma unroll
        for (int op = 0; op < 32; op++) {
            float v0, v1; upk2(acc[op], v0, v1);
            h1[2 * op]     = fmaxf(v0, 0.0f);
            h1[2 * op + 1] = fmaxf(v1, 0.0f);
        }
    }

    // ---- layer 2: 64 -> 128, streamed to scratch per 64-ch chunk ----
    float4* h2o = g_h2 + (size_t)g * 1024;     // 32 chunks x 32 lanes
#pragma unroll
    for (int oc = 0; oc < 2; oc++) {
        unsigned long long acc[32];
#pragma unroll
        for (int opl = 0; opl < 32; opl++) acc[opl] = bb2[oc * 32 + opl];
#pragma unroll
        for (int ip = 0; ip < 32; ip++) {
            unsigned long long hd0 = pk2(h1[2 * ip],     h1[2 * ip]);
            unsigned long long hd1 = pk2(h1[2 * ip + 1], h1[2 * ip + 1]);
#pragma unroll
            for (int opl = 0; opl < 32; opl++) {
                ulonglong2 w = w2p[(oc * 32 + opl) * 32 + ip];
                fma2(acc[opl], w.x, hd0);
                fma2(acc[opl], w.y, hd1);
            }
        }
#pragma unroll
        for (int t = 0; t < 16; t++) {
            float v0, v1, v2, v3;
            upk2(acc[2 * t],     v0, v1);
            upk2(acc[2 * t + 1], v2, v3);
            float4 o;
            o.x = fmaxf(v0, 0.0f); o.y = fmaxf(v1, 0.0f);
            o.z = fmaxf(v2, 0.0f); o.w = fmaxf(v3, 0.0f);
            h2o[(oc * 16 + t) * 32 + lane] = o;
        }
    }
}

// ------------------------------------------------------------------
// Kernel 3B: layer 3 via tf32 mma.sync (m16n8k8).
// Per group: D[256ch x 32k] = W3[256x128] @ h2[128x32], bias in acc
// init, relu, max over k. Warp w owns channels [w*32, w*32+32):
// W3 fragments STATIONARY in registers (loaded once per CTA -> no
// per-group weight LDS stream). h2 staged tf32-rounded into shared.
// Fragment maps (PTX m16n8k8.row.col, lane l, tig=l&3, gid=l>>2):
//   A: a0(r=gid,   c=tig) a1(r=gid+8, c=tig) a2(c=tig+4) a3(both)
//   B: b0(row=tig, col=gid) b1(row=tig+4, col=gid)
//   D: d0(r=gid, c=2tig) d1(c=2tig+1) d2(r=gid+8,...) d3
// ------------------------------------------------------------------
__global__ __launch_bounds__(256, 1)
void mlp3_kernel(const float* __restrict__ W3, const float* __restrict__ b3,
                 float* __restrict__ feats_out)
{
    __shared__ float h2s[128 * 33];            // [ip][k], stride 33
    const int tid  = threadIdx.x;
    const int lane = tid & 31;
    const int wid  = tid >> 5;
    const int mb   = wid * 32;                 // warp's channel base
    const int tig  = lane & 3;
    const int gid  = lane >> 2;

    // ---- load A fragments (tf32) + bias, once per CTA ----
    uint32_t a[2][16][4];
#pragma unroll
    for (int mt = 0; mt < 2; mt++) {
#pragma unroll
        for (int ks = 0; ks < 16; ks++) {
            const float* wb = W3 + (size_t)(mb + mt * 16 + gid) * 128 + ks * 8 + tig;
            a[mt][ks][0] = __float_as_uint(tf32r(wb[0]));
            a[mt][ks][1] = __float_as_uint(tf32r(wb[8 * 128]));
            a[mt][ks][2] = __float_as_uint(tf32r(wb[4]));
            a[mt][ks][3] = __float_as_uint(tf32r(wb[8 * 128 + 4]));
        }
    }
    float bz[2][2];
#pragma unroll
    for (int mt = 0; mt < 2; mt++) {
        bz[mt][0] = b3[mb + mt * 16 + gid];
        bz[mt][1] = b3[mb + mt * 16 + 8 + gid];
    }

    for (int gg = 0; gg < 8; gg++) {
        const int g = blockIdx.x * 8 + gg;

        // ---- stage h2 (tf32-rounded) into shared [ip][k] ----
        __syncthreads();                       // protect h2s reuse
        {
            const float4* src = g_h2 + (size_t)g * 1024;
            for (int t = tid; t < 1024; t += 256) {
                float4 v = src[t];
                int chunk = t >> 5, k = t & 31;
                int ip0 = chunk * 4;
                h2s[(ip0 + 0) * 33 + k] = tf32r(v.x);
                h2s[(ip0 + 1) * 33 + k] = tf32r(v.y);
                h2s[(ip0 + 2) * 33 + k] = tf32r(v.z);
                h2s[(ip0 + 3) * 33 + k] = tf32r(v.w);
            }
        }
        __syncthreads();

        // ---- mma: 2 m-tiles x 4 n-tiles x 16 k-steps ----
        float d[2][4][4];
#pragma unroll
        for (int mt = 0; mt < 2; mt++)
#pragma unroll
            for (int nt = 0; nt < 4; nt++) {
                d[mt][nt][0] = bz[mt][0]; d[mt][nt][1] = bz[mt][0];
                d[mt][nt][2] = bz[mt][1]; d[mt][nt][3] = bz[mt][1];
            }
#pragma unroll
        for (int ks = 0; ks < 16; ks++) {
#pragma unroll
            for (int nt = 0; nt < 4; nt++) {
                uint32_t b0 = __float_as_uint(h2s[(ks * 8 + tig) * 33 + nt * 8 + gid]);
                uint32_t b1 = __float_as_uint(h2s[(ks * 8 + tig + 4) * 33 + nt * 8 + gid]);
#pragma unroll
                for (int mt = 0; mt < 2; mt++)
                    mma_tf32(d[mt][nt][0], d[mt][nt][1], d[mt][nt][2], d[mt][nt][3],
                             a[mt][ks][0], a[mt][ks][1], a[mt][ks][2], a[mt][ks][3],
                             b0, b1);
            }
        }

        // ---- relu + max over k (cols), write channels ----
#pragma unroll
        for (int mt = 0; mt < 2; mt++) {
            float v0 = 0.0f, v1 = 0.0f;        // relu floor is 0
#pragma unroll
            for (int nt = 0; nt < 4; nt++) {
                v0 = fmaxf(v0, fmaxf(d[mt][nt][0], d[mt][nt][1]));
                v1 = fmaxf(v1, fmaxf(d[mt][nt][2], d[mt][nt][3]));
            }
#pragma unroll
            for (int off = 1; off <= 2; off <<= 1) {
                v0 = fmaxf(v0, __shfl_xor_sync(0xffffffffu, v0, off));
                v1 = fmaxf(v1, __shfl_xor_sync(0xffffffffu, v1, off));
            }
            if (tig == 0) {
                feats_out[(size_t)g * 256 + mb + mt * 16 + gid]     = v0;
                feats_out[(size_t)g * 256 + mb + mt * 16 + 8 + gid] = v1;
            }
        }
    }
}

// ------------------------------------------------------------------
extern "C" void kernel_launch(void* const* d_in, const int* in_sizes, int n_in,
                              void* d_out, int out_size)
{
    const float* xyz      = (const float*)d_in[0];
    const float* features = (const float*)d_in[1];
    const float* W1 = (const float*)d_in[2];
    const float* b1 = (const float*)d_in[3];
    const float* W2 = (const float*)d_in[4];
    const float* b2 = (const float*)d_in[5];
    const float* W3 = (const float*)d_in[6];
    const float* b3 = (const float*)d_in[7];

    float* out    = (float*)d_out;
    float* newxyz = out;                         // [B,S,3] = 24576 floats
    float* feats  = out + (size_t)BB * SS * 3;   // [B,S,256]

    cudaFuncSetAttribute(fps_kernel, cudaFuncAttributeMaxDynamicSharedMemorySize,
                         NN * (int)sizeof(float4));
    cudaFuncSetAttribute(mlp12_kernel, cudaFuncAttributeMaxDynamicSharedMemorySize,
                         A_FLOATS * (int)sizeof(float));

    fps_kernel<<<BB, 1024, NN * sizeof(float4)>>>(xyz, newxyz);
    ballq_kernel<<<(BB * SS * 32) / 256, 256>>>(xyz, newxyz);
    mlp12_kernel<<<(BB * SS) / 8, 256, A_FLOATS * sizeof(float)>>>(
        xyz, features, W1, b1, W2, b2, newxyz);
    mlp3_kernel<<<(BB * SS) / 8, 256>>>(W3, b3, feats);
}

// round 14
// speedup vs baseline: 1.4995x; 1.1604x over previous
#include <cuda_runtime.h>
#include <cstdint>
#include <cstddef>

#define BB 4
#define NN 8192
#define SS 2048
#define KK 32
#define DD 64

// group indices scratch: [B*S, K]
__device__ int g_grp[BB * SS * KK];

// ---------------- packed f32x2 helpers (per-lane IEEE == scalar) ----------
__device__ __forceinline__ unsigned long long pk2(float lo, float hi) {
    unsigned long long r;
    asm("mov.b64 %0, {%1, %2};" : "=l"(r) : "f"(lo), "f"(hi));
    return r;
}
__device__ __forceinline__ void upk2(unsigned long long v, float& lo, float& hi) {
    asm("mov.b64 {%0, %1}, %2;" : "=f"(lo), "=f"(hi) : "l"(v));
}
__device__ __forceinline__ unsigned long long add2(unsigned long long a, unsigned long long b) {
    unsigned long long r;
    asm("add.rn.f32x2 %0, %1, %2;" : "=l"(r) : "l"(a), "l"(b));
    return r;
}
__device__ __forceinline__ unsigned long long mul2(unsigned long long a, unsigned long long b) {
    unsigned long long r;
    asm("mul.rn.f32x2 %0, %1, %2;" : "=l"(r) : "l"(a), "l"(b));
    return r;
}

// TF32 rounding (round-to-nearest-away, as cuBLAS uses for tf32 operands).
__device__ __forceinline__ float tf32r(float x)
{
    float r;
    asm("cvt.rna.tf32.f32 %0, %1;" : "=f"(r) : "f"(x));
    return r;
}

// m16n8k8 tf32 MMA, D = A*B + D (f32 accumulate).
__device__ __forceinline__ void mma_tf32(float& d0, float& d1, float& d2, float& d3,
                                         uint32_t a0, uint32_t a1, uint32_t a2, uint32_t a3,
                                         uint32_t b0, uint32_t b1)
{
    asm("mma.sync.aligned.m16n8k8.row.col.f32.tf32.tf32.f32 "
        "{%0,%1,%2,%3},{%4,%5,%6,%7},{%8,%9},{%0,%1,%2,%3};"
        : "+f"(d0), "+f"(d1), "+f"(d2), "+f"(d3)
        : "r"(a0), "r"(a1), "r"(a2), "r"(a3), "r"(b0), "r"(b1));
}

// ------------------------------------------------------------------
// Kernel 1: farthest point sampling (unchanged, verified bit-exact).
// ------------------------------------------------------------------
__global__ __launch_bounds__(1024, 1)
void fps_kernel(const float* __restrict__ xyz, float* __restrict__ newxyz)
{
    extern __shared__ float4 sxyz[];           // 8192 * 16B = 128KB
    __shared__ unsigned int sd[2][32];
    __shared__ int          si[2][32];

    const int b    = blockIdx.x;
    const int tid  = threadIdx.x;
    const int lane = tid & 31;
    const float* xb = xyz + (size_t)b * NN * 3;

    unsigned long long pxp[4], pyp[4], pzp[4];
    float dist[8];
#pragma unroll
    for (int j = 0; j < 4; j++) {
        int p0 = tid * 8 + 2 * j;
        float x0 = xb[p0 * 3 + 0], y0 = xb[p0 * 3 + 1], z0 = xb[p0 * 3 + 2];
        float x1 = xb[p0 * 3 + 3], y1 = xb[p0 * 3 + 4], z1 = xb[p0 * 3 + 5];
        pxp[j] = pk2(x0, x1); pyp[j] = pk2(y0, y1); pzp[j] = pk2(z0, z1);
        dist[2 * j] = 1e10f; dist[2 * j + 1] = 1e10f;
        sxyz[p0]     = make_float4(x0, y0, z0, 0.0f);
        sxyz[p0 + 1] = make_float4(x1, y1, z1, 0.0f);
    }
    __syncthreads();

    int cur = 0;
    for (int s = 0; s < SS; s++) {
        float4 c4 = sxyz[cur];                 // LDS.128 broadcast
        if (tid == 0) {
            float* o = newxyz + ((size_t)b * SS + s) * 3;
            o[0] = c4.x; o[1] = c4.y; o[2] = c4.z;
        }
        unsigned long long cx2 = pk2(-c4.x, -c4.x);
        unsigned long long cy2 = pk2(-c4.y, -c4.y);
        unsigned long long cz2 = pk2(-c4.z, -c4.z);
        float bv = -1.0f;
#pragma unroll
        for (int j = 0; j < 4; j++) {
            unsigned long long dx = add2(pxp[j], cx2);
            unsigned long long dy = add2(pyp[j], cy2);
            unsigned long long dz = add2(pzp[j], cz2);
            unsigned long long dd = add2(add2(mul2(dx, dx), mul2(dy, dy)),
                                         mul2(dz, dz));
            float dl, dh; upk2(dd, dl, dh);
            float n0 = fminf(dist[2 * j],     dl);
            float n1 = fminf(dist[2 * j + 1], dh);
            dist[2 * j]     = n0;
            dist[2 * j + 1] = n1;
            bv = fmaxf(bv, fmaxf(n0, n1));
        }
        int bi = 0;
#pragma unroll
        for (int j = 7; j >= 0; j--) if (dist[j] == bv) bi = j;

        unsigned db = __float_as_uint(bv);     // dist>=0: uint order == float order
        unsigned wm = __reduce_max_sync(0xffffffffu, db);
        unsigned bl = __ballot_sync(0xffffffffu, db == wm);
        int src  = __ffs(bl) - 1;              // smallest lane == smallest index
        int widx = __shfl_sync(0xffffffffu, tid * 8 + bi, src);

        int par = s & 1;
        if (lane == 0) { sd[par][tid >> 5] = wm; si[par][tid >> 5] = widx; }
        __syncthreads();
        unsigned vd = sd[par][lane];
        int      vi = si[par][lane];
        unsigned m2 = __reduce_max_sync(0xffffffffu, vd);
        unsigned b2 = __ballot_sync(0xffffffffu, vd == m2);
        int s2 = __ffs(b2) - 1;                // smallest warp == smallest index
        cur = __shfl_sync(0xffffffffu, vi, s2);
    }
}

// ------------------------------------------------------------------
// Kernel 2: ball query (unchanged, verified bit-exact).
// ------------------------------------------------------------------
__global__ __launch_bounds__(256)
void ballq_kernel(const float* __restrict__ xyz,
                  const float* __restrict__ newxyz)
{
    const int w    = (blockIdx.x * blockDim.x + threadIdx.x) >> 5;
    const int lane = threadIdx.x & 31;
    const int b = w >> 11;                      // w / 2048
    const float* xb = xyz + (size_t)b * NN * 3;
    const float* nw = newxyz + (size_t)w * 3;

    float nx = nw[0], ny = nw[1], nz = nw[2];
    float nsq = __fadd_rn(__fadd_rn(__fmul_rn(nx, nx), __fmul_rn(ny, ny)),
                          __fmul_rn(nz, nz));
    int cnt = 0;
    int first = 0;
    int* g = g_grp + (size_t)w * KK;

    for (int base = 0; base < NN; base += 32) {
        int p = base + lane;
        float x = xb[p * 3 + 0];
        float y = xb[p * 3 + 1];
        float z = xb[p * 3 + 2];
        float xsq = __fadd_rn(__fadd_rn(__fmul_rn(x, x), __fmul_rn(y, y)),
                              __fmul_rn(z, z));
        float dot = __fmaf_rn(nz, z, __fmaf_rn(ny, y, __fmul_rn(nx, x)));
        float sq  = __fsub_rn(__fadd_rn(nsq, xsq), __fmul_rn(2.0f, dot));
        bool hit  = !(sq > 0.04f);
        unsigned m = __ballot_sync(0xffffffffu, hit);
        if (cnt == 0 && m) first = base + __ffs(m) - 1;
        int pos = cnt + __popc(m & ((1u << lane) - 1u));
        if (hit && pos < KK) g[pos] = p;
        cnt += __popc(m);
        if (cnt >= KK) break;
    }
    if (cnt < KK) {
        for (int k = cnt + lane; k < KK; k += 32) g[k] = first;
    }
}

// ------------------------------------------------------------------
// Kernel 3: FUSED gather + 3-layer MLP (all tf32 mma) + max-pool.
// 8 warps/CTA, 8 groups/CTA. All weight fragments register-stationary
// (loaded once per CTA). Activations tf32-rounded in shared:
//   h0s [72][33]  (rows 0-2 xyz diff, 3-66 features, 67-71 zero pad)
//   h1s [64][33]  h2s [128][33]
// Per group: [sync][gather][sync][L1 w0-3][sync][L2][sync][L3+out].
// Fragment maps (m16n8k8.row.col, lane l, tig=l&3, gid=l>>2):
//   A: a0(r=gid,c=tig) a1(r=gid+8) a2(c=tig+4) a3(both)
//   B: b0(row=tig,col=gid) b1(row=tig+4)
//   D: d0(r=gid,c=2tig) d1(c=2tig+1) d2(r=gid+8) d3
// ------------------------------------------------------------------
__global__ __launch_bounds__(256, 1)
void mlp_fused_kernel(const float* __restrict__ xyz,
                      const float* __restrict__ features,
                      const float* __restrict__ W1, const float* __restrict__ b1,
                      const float* __restrict__ W2, const float* __restrict__ b2,
                      const float* __restrict__ W3, const float* __restrict__ b3,
                      const float* __restrict__ newxyz,
                      float* __restrict__ feats_out)
{
    __shared__ float h0s[72 * 33];
    __shared__ float h1s[64 * 33];
    __shared__ float h2s[128 * 33];
    __shared__ int   sgi[32];
    __shared__ float sctr[3];

    const int tid  = threadIdx.x;
    const int lane = tid & 31;
    const int wid  = tid >> 5;
    const int tig  = lane & 3;
    const int gid  = lane >> 2;

    // zero h0s pad rows 67..71 once (never rewritten)
    for (int t = tid; t < 5 * 33; t += 256) h0s[67 * 33 + t] = 0.0f;

    // ---- W1 fragments: warps 0-3 own 16 channels each; K 67 -> 72 pad ----
    uint32_t a1f[9][4];
    float bz1_0 = 0.0f, bz1_1 = 0.0f;
    if (wid < 4) {
        int mb = wid * 16;
#pragma unroll
        for (int ks = 0; ks < 9; ks++) {
            int k0 = ks * 8 + tig, k1 = k0 + 4;
            const float* r0 = W1 + (size_t)(mb + gid) * 67;
            const float* r1 = W1 + (size_t)(mb + 8 + gid) * 67;
            a1f[ks][0] = (k0 < 67) ? __float_as_uint(tf32r(r0[k0])) : 0u;
            a1f[ks][1] = (k0 < 67) ? __float_as_uint(tf32r(r1[k0])) : 0u;
            a1f[ks][2] = (k1 < 67) ? __float_as_uint(tf32r(r0[k1])) : 0u;
            a1f[ks][3] = (k1 < 67) ? __float_as_uint(tf32r(r1[k1])) : 0u;
        }
        bz1_0 = b1[mb + gid];
        bz1_1 = b1[mb + 8 + gid];
    }

    // ---- W2 fragments: all 8 warps own 16 channels each; K=64 ----
    uint32_t a2f[8][4];
    {
        int mb = wid * 16;
#pragma unroll
        for (int ks = 0; ks < 8; ks++) {
            const float* r0 = W2 + (size_t)(mb + gid) * 64 + ks * 8 + tig;
            const float* r1 = W2 + (size_t)(mb + 8 + gid) * 64 + ks * 8 + tig;
            a2f[ks][0] = __float_as_uint(tf32r(r0[0]));
            a2f[ks][1] = __float_as_uint(tf32r(r1[0]));
            a2f[ks][2] = __float_as_uint(tf32r(r0[4]));
            a2f[ks][3] = __float_as_uint(tf32r(r1[4]));
        }
    }
    const float bz2_0 = b2[wid * 16 + gid];
    const float bz2_1 = b2[wid * 16 + 8 + gid];

    // ---- W3 fragments: all warps own 32 channels (2 m-tiles); K=128 ----
    uint32_t a3f[2][16][4];
    {
        int mb = wid * 32;
#pragma unroll
        for (int mt = 0; mt < 2; mt++)
#pragma unroll
            for (int ks = 0; ks < 16; ks++) {
                const float* wb = W3 + (size_t)(mb + mt * 16 + gid) * 128 + ks * 8 + tig;
                a3f[mt][ks][0] = __float_as_uint(tf32r(wb[0]));
                a3f[mt][ks][1] = __float_as_uint(tf32r(wb[8 * 128]));
                a3f[mt][ks][2] = __float_as_uint(tf32r(wb[4]));
                a3f[mt][ks][3] = __float_as_uint(tf32r(wb[8 * 128 + 4]));
            }
    }
    float bz3[2][2];
#pragma unroll
    for (int mt = 0; mt < 2; mt++) {
        bz3[mt][0] = b3[wid * 32 + mt * 16 + gid];
        bz3[mt][1] = b3[wid * 32 + mt * 16 + 8 + gid];
    }

    for (int gg = 0; gg < 8; gg++) {
        const int g = blockIdx.x * 8 + gg;
        const int b = g >> 11;

        __syncthreads();                       // prev iter fully done
        if (tid < 32) sgi[tid] = g_grp[(size_t)g * KK + tid];
        if (tid < 3)  sctr[tid] = newxyz[(size_t)g * 3 + tid];
        __syncthreads();

        // ---- gather h0 (tf32-rounded): xyz diff rows 0-2, features 3-66 ----
        if (tid < 96) {
            int c = tid >> 5, k = tid & 31;
            float v = xyz[((size_t)b * NN + sgi[k]) * 3 + c] - sctr[c];
            h0s[c * 33 + k] = tf32r(v);
        }
        for (int t = tid; t < 512; t += 256) {
            int k = t >> 4, q = t & 15;        // coalesced: row-chunk per thread
            const float4 v = *(const float4*)(features +
                                  ((size_t)b * NN + sgi[k]) * DD + q * 4);
            float* dst = &h0s[(3 + 4 * q) * 33 + k];
            dst[0]      = tf32r(v.x);
            dst[33]     = tf32r(v.y);
            dst[66]     = tf32r(v.z);
            dst[99]     = tf32r(v.w);
        }
        __syncthreads();

        // ---- layer 1: 72(k) -> 64, warps 0-3 ----
        if (wid < 4) {
            float d[4][4];
#pragma unroll
            for (int nt = 0; nt < 4; nt++) {
                d[nt][0] = bz1_0; d[nt][1] = bz1_0;
                d[nt][2] = bz1_1; d[nt][3] = bz1_1;
            }
#pragma unroll
            for (int ks = 0; ks < 9; ks++) {
#pragma unroll
                for (int nt = 0; nt < 4; nt++) {
                    uint32_t b0 = __float_as_uint(h0s[(ks * 8 + tig) * 33 + nt * 8 + gid]);
                    uint32_t b1v = __float_as_uint(h0s[(ks * 8 + tig + 4) * 33 + nt * 8 + gid]);
                    mma_tf32(d[nt][0], d[nt][1], d[nt][2], d[nt][3],
                             a1f[ks][0], a1f[ks][1], a1f[ks][2], a1f[ks][3], b0, b1v);
                }
            }
            int mb = wid * 16;
#pragma unroll
            for (int nt = 0; nt < 4; nt++) {
                h1s[(mb + gid) * 33 + nt * 8 + 2 * tig]         = tf32r(fmaxf(d[nt][0], 0.0f));
                h1s[(mb + gid) * 33 + nt * 8 + 2 * tig + 1]     = tf32r(fmaxf(d[nt][1], 0.0f));
                h1s[(mb + 8 + gid) * 33 + nt * 8 + 2 * tig]     = tf32r(fmaxf(d[nt][2], 0.0f));
                h1s[(mb + 8 + gid) * 33 + nt * 8 + 2 * tig + 1] = tf32r(fmaxf(d[nt][3], 0.0f));
            }
        }
        __syncthreads();

        // ---- layer 2: 64 -> 128, all warps (16 ch each) ----
        {
            float d[4][4];
#pragma unroll
            for (int nt = 0; nt < 4; nt++) {
                d[nt][0] = bz2_0; d[nt][1] = bz2_0;
                d[nt][2] = bz2_1; d[nt][3] = bz2_1;
            }
#pragma unroll
            for (int ks = 0; ks < 8; ks++) {
#pragma unroll
                for (int nt = 0; nt < 4; nt++) {
                    uint32_t b0 = __float_as_uint(h1s[(ks * 8 + tig) * 33 + nt * 8 + gid]);
                    uint32_t b1v = __float_as_uint(h1s[(ks * 8 + tig + 4) * 33 + nt * 8 + gid]);
                    mma_tf32(d[nt][0], d[nt][1], d[nt][2], d[nt][3],
                             a2f[ks][0], a2f[ks][1], a2f[ks][2], a2f[ks][3], b0, b1v);
                }
            }
            int mb = wid * 16;
#pragma unroll
            for (int nt = 0; nt < 4; nt++) {
                h2s[(mb + gid) * 33 + nt * 8 + 2 * tig]         = tf32r(fmaxf(d[nt][0], 0.0f));
                h2s[(mb + gid) * 33 + nt * 8 + 2 * tig + 1]     = tf32r(fmaxf(d[nt][1], 0.0f));
                h2s[(mb + 8 + gid) * 33 + nt * 8 + 2 * tig]     = tf32r(fmaxf(d[nt][2], 0.0f));
                h2s[(mb + 8 + gid) * 33 + nt * 8 + 2 * tig + 1] = tf32r(fmaxf(d[nt][3], 0.0f));
            }
        }
        __syncthreads();

        // ---- layer 3: 128 -> 256, all warps (32 ch), relu+max epilogue ----
        {
            float d[2][4][4];
#pragma unroll
            for (int mt = 0; mt < 2; mt++)
#pragma unroll
                for (int nt = 0; nt < 4; nt++) {
                    d[mt][nt][0] = bz3[mt][0]; d[mt][nt][1] = bz3[mt][0];
                    d[mt][nt][2] = bz3[mt][1]; d[mt][nt][3] = bz3[mt][1];
                }
#pragma unroll
            for (int ks = 0; ks < 16; ks++) {
#pragma unroll
                for (int nt = 0; nt < 4; nt++) {
                    uint32_t b0 = __float_as_uint(h2s[(ks * 8 + tig) * 33 + nt * 8 + gid]);
                    uint32_t b1v = __float_as_uint(h2s[(ks * 8 + tig + 4) * 33 + nt * 8 + gid]);
#pragma unroll
                    for (int mt = 0; mt < 2; mt++)
                        mma_tf32(d[mt][nt][0], d[mt][nt][1], d[mt][nt][2], d[mt][nt][3],
                                 a3f[mt][ks][0], a3f[mt][ks][1], a3f[mt][ks][2], a3f[mt][ks][3],
                                 b0, b1v);
                }
            }
            int mb = wid * 32;
#pragma unroll
            for (int mt = 0; mt < 2; mt++) {
                float v0 = 0.0f, v1 = 0.0f;    // relu floor
#pragma unroll
                for (int nt = 0; nt < 4; nt++) {
                    v0 = fmaxf(v0, fmaxf(d[mt][nt][0], d[mt][nt][1]));
                    v1 = fmaxf(v1, fmaxf(d[mt][nt][2], d[mt][nt][3]));
                }
#pragma unroll
                for (int off = 1; off <= 2; off <<= 1) {
                    v0 = fmaxf(v0, __shfl_xor_sync(0xffffffffu, v0, off));
                    v1 = fmaxf(v1, __shfl_xor_sync(0xffffffffu, v1, off));
                }
                if (tig == 0) {
                    feats_out[(size_t)g * 256 + mb + mt * 16 + gid]     = v0;
                    feats_out[(size_t)g * 256 + mb + mt * 16 + 8 + gid] = v1;
                }
            }
        }
    }
}

// ------------------------------------------------------------------
extern "C" void kernel_launch(void* const* d_in, const int* in_sizes, int n_in,
                              void* d_out, int out_size)
{
    const float* xyz      = (const float*)d_in[0];
    const float* features = (const float*)d_in[1];
    const float* W1 = (const float*)d_in[2];
    const float* b1 = (const float*)d_in[3];
    const float* W2 = (const float*)d_in[4];
    const float* b2 = (const float*)d_in[5];
    const float* W3 = (const float*)d_in[6];
    const float* b3 = (const float*)d_in[7];

    float* out    = (float*)d_out;
    float* newxyz = out;                         // [B,S,3] = 24576 floats
    float* feats  = out + (size_t)BB * SS * 3;   // [B,S,256]

    cudaFuncSetAttribute(fps_kernel, cudaFuncAttributeMaxDynamicSharedMemorySize,
                         NN * (int)sizeof(float4));

    fps_kernel<<<BB, 1024, NN * sizeof(float4)>>>(xyz, newxyz);
    ballq_kernel<<<(BB * SS * 32) / 256, 256>>>(xyz, newxyz);
    mlp_fused_kernel<<<(BB * SS) / 8, 256>>>(
        xyz, features, W1, b1, W2, b2, W3, b3, newxyz, feats);
}

// round 15
// speedup vs baseline: 1.8651x; 1.2438x over previous
#include <cuda_runtime.h>
#include <cstdint>
#include <cstddef>

#define BB 4
#define NN 8192
#define SS 2048
#define KK 32
#define DD 64
#define NCONS  144            // consumer CTAs
#define NCHUNK 1024           // 8192 groups / 8 per chunk

// cross-CTA progress: fps CTA b publishes #centroids written for batch b
__device__ volatile int g_progress[BB];

// ---------------- packed f32x2 helpers (per-lane IEEE == scalar) ----------
__device__ __forceinline__ unsigned long long pk2(float lo, float hi) {
    unsigned long long r;
    asm("mov.b64 %0, {%1, %2};" : "=l"(r) : "f"(lo), "f"(hi));
    return r;
}
__device__ __forceinline__ void upk2(unsigned long long v, float& lo, float& hi) {
    asm("mov.b64 {%0, %1}, %2;" : "=f"(lo), "=f"(hi) : "l"(v));
}
__device__ __forceinline__ unsigned long long add2(unsigned long long a, unsigned long long b) {
    unsigned long long r;
    asm("add.rn.f32x2 %0, %1, %2;" : "=l"(r) : "l"(a), "l"(b));
    return r;
}
__device__ __forceinline__ unsigned long long mul2(unsigned long long a, unsigned long long b) {
    unsigned long long r;
    asm("mul.rn.f32x2 %0, %1, %2;" : "=l"(r) : "l"(a), "l"(b));
    return r;
}

// TF32 rounding (round-to-nearest-away, as cuBLAS uses for tf32 operands).
__device__ __forceinline__ float tf32r(float x)
{
    float r;
    asm("cvt.rna.tf32.f32 %0, %1;" : "=f"(r) : "f"(x));
    return r;
}

// m16n8k8 tf32 MMA, D = A*B + D (f32 accumulate).
__device__ __forceinline__ void mma_tf32(float& d0, float& d1, float& d2, float& d3,
                                         uint32_t a0, uint32_t a1, uint32_t a2, uint32_t a3,
                                         uint32_t b0, uint32_t b1)
{
    asm("mma.sync.aligned.m16n8k8.row.col.f32.tf32.tf32.f32 "
        "{%0,%1,%2,%3},{%4,%5,%6,%7},{%8,%9},{%0,%1,%2,%3};"
        : "+f"(d0), "+f"(d1), "+f"(d2), "+f"(d3)
        : "r"(a0), "r"(a1), "r"(a2), "r"(a3), "r"(b0), "r"(b1));
}

__global__ void init_kernel()
{
    if (threadIdx.x < BB) g_progress[threadIdx.x] = 0;
}

// ------------------------------------------------------------------
// ONE persistent kernel, grid = 4 + 144 = 148 CTAs, 256 thr, 131KB smem
// (1 CTA/SM -> all resident -> polling is deadlock-free).
// CTA 0-3:   FPS for batch b (bit-exact, 32 pts/thread, publishes progress).
// CTA 4-147: consumer cc: for chunks m = cc, cc+144, ...:
//            wait progress >= 2m+2, warp-per-group ball query (smem),
//            fused tf32-mma 3-layer MLP + k-max for the 8 groups.
// ------------------------------------------------------------------
__global__ __launch_bounds__(256, 1)
void fused_kernel(const float* __restrict__ xyz,
                  const float* __restrict__ features,
                  const float* __restrict__ W1, const float* __restrict__ b1,
                  const float* __restrict__ W2, const float* __restrict__ b2,
                  const float* __restrict__ W3, const float* __restrict__ b3,
                  float* __restrict__ newxyz,
                  float* __restrict__ feats_out)
{
    extern __shared__ float smem[];
    __shared__ unsigned skey_d[8];
    __shared__ int      skey_i[8];
    __shared__ int      scur;

    const int tid  = threadIdx.x;
    const int lane = tid & 31;
    const int wid  = tid >> 5;

    if (blockIdx.x < BB) {
        // ================= FPS (bit-exact, verified math) =================
        const int b = blockIdx.x;
        float4* sxyz = (float4*)smem;          // 8192 * 16B = 128KB
        const float* xb = xyz + (size_t)b * NN * 3;

        unsigned long long pxp[16], pyp[16], pzp[16];
        float dist[32];
#pragma unroll
        for (int j = 0; j < 16; j++) {
            int p0 = tid * 32 + 2 * j;
            float x0 = xb[p0 * 3 + 0], y0 = xb[p0 * 3 + 1], z0 = xb[p0 * 3 + 2];
            float x1 = xb[p0 * 3 + 3], y1 = xb[p0 * 3 + 4], z1 = xb[p0 * 3 + 5];
            pxp[j] = pk2(x0, x1); pyp[j] = pk2(y0, y1); pzp[j] = pk2(z0, z1);
            dist[2 * j] = 1e10f; dist[2 * j + 1] = 1e10f;
            sxyz[p0]     = make_float4(x0, y0, z0, 0.0f);
            sxyz[p0 + 1] = make_float4(x1, y1, z1, 0.0f);
        }
        __syncthreads();

        int cur = 0;
        for (int s = 0; s < SS; s++) {
            float4 c4 = sxyz[cur];
            if (tid == 0) {
                float* o = newxyz + ((size_t)b * SS + s) * 3;
                o[0] = c4.x; o[1] = c4.y; o[2] = c4.z;
                if ((s & 7) == 7) {            // publish every 8 centroids
                    __threadfence();
                    g_progress[b] = s + 1;
                }
            }
            unsigned long long cx2 = pk2(-c4.x, -c4.x);
            unsigned long long cy2 = pk2(-c4.y, -c4.y);
            unsigned long long cz2 = pk2(-c4.z, -c4.z);
            float bv = -1.0f;
            int   bi = 0;
#pragma unroll
            for (int j = 0; j < 16; j++) {
                unsigned long long dx = add2(pxp[j], cx2);
                unsigned long long dy = add2(pyp[j], cy2);
                unsigned long long dz = add2(pzp[j], cz2);
                unsigned long long dd = add2(add2(mul2(dx, dx), mul2(dy, dy)),
                                             mul2(dz, dz));
                float dl, dh; upk2(dd, dl, dh);
                float n0 = fminf(dist[2 * j],     dl);
                float n1 = fminf(dist[2 * j + 1], dh);
                dist[2 * j]     = n0;
                dist[2 * j + 1] = n1;
                if (n0 > bv) { bv = n0; bi = 2 * j; }      // strict > with
                if (n1 > bv) { bv = n1; bi = 2 * j + 1; }  // ascending j:
            }                                               // first-index max
            unsigned db = __float_as_uint(bv); // dist>=0: uint order == float
            unsigned wm = __reduce_max_sync(0xffffffffu, db);
            unsigned bl = __ballot_sync(0xffffffffu, db == wm);
            int src  = __ffs(bl) - 1;          // smallest lane == smallest idx
            int widx = __shfl_sync(0xffffffffu, tid * 32 + bi, src);
            if (lane == 0) { skey_d[wid] = wm; skey_i[wid] = widx; }
            __syncthreads();
            if (wid == 0) {
                unsigned vd = (lane < 8) ? skey_d[lane] : 0u;
                int      vi = (lane < 8) ? skey_i[lane] : 0;
                unsigned m2 = __reduce_max_sync(0xffffffffu, vd);
                unsigned b2 = __ballot_sync(0xffffffffu, vd == m2);
                int s2  = __ffs(b2) - 1;       // smallest warp == smallest idx
                int win = __shfl_sync(0xffffffffu, vi, s2);
                if (lane == 0) scur = win;
            }
            __syncthreads();
            cur = scur;
        }
        return;
    }

    // ===================== consumer: ballq + fused MLP =====================
    const int cc  = blockIdx.x - BB;           // 0..143
    const int tig = lane & 3;
    const int gid = lane >> 2;

    float* h0s  = smem;                        // 72*33 = 2376 floats
    float* h1s  = smem + 2376;                 // 64*33 = 2112
    float* h2s  = smem + 4488;                 // 128*33 = 4224
    int*   sgi  = (int*)(smem + 8712);         // 8*32 neighbor idx
    float* sctr = smem + 8968;                 // 8*3 centroids

    // zero h0s pad rows 67..71 once (never rewritten)
    for (int t = tid; t < 5 * 33; t += 256) h0s[67 * 33 + t] = 0.0f;

    // ---- W1 fragments: warps 0-3 own 16 channels; K 67 -> 72 zero pad ----
    uint32_t a1f[9][4];
    float bz1_0 = 0.0f, bz1_1 = 0.0f;
    if (wid < 4) {
        int mb = wid * 16;
#pragma unroll
        for (int ks = 0; ks < 9; ks++) {
            int k0 = ks * 8 + tig, k1 = k0 + 4;
            const float* r0 = W1 + (size_t)(mb + gid) * 67;
            const float* r1 = W1 + (size_t)(mb + 8 + gid) * 67;
            a1f[ks][0] = (k0 < 67) ? __float_as_uint(tf32r(r0[k0])) : 0u;
            a1f[ks][1] = (k0 < 67) ? __float_as_uint(tf32r(r1[k0])) : 0u;
            a1f[ks][2] = (k1 < 67) ? __float_as_uint(tf32r(r0[k1])) : 0u;
            a1f[ks][3] = (k1 < 67) ? __float_as_uint(tf32r(r1[k1])) : 0u;
        }
        bz1_0 = b1[mb + gid];
        bz1_1 = b1[mb + 8 + gid];
    }
    // ---- W2 fragments: all 8 warps own 16 channels; K=64 ----
    uint32_t a2f[8][4];
    {
        int mb = wid * 16;
#pragma unroll
        for (int ks = 0; ks < 8; ks++) {
            const float* r0 = W2 + (size_t)(mb + gid) * 64 + ks * 8 + tig;
            const float* r1 = W2 + (size_t)(mb + 8 + gid) * 64 + ks * 8 + tig;
            a2f[ks][0] = __float_as_uint(tf32r(r0[0]));
            a2f[ks][1] = __float_as_uint(tf32r(r1[0]));
            a2f[ks][2] = __float_as_uint(tf32r(r0[4]));
            a2f[ks][3] = __float_as_uint(tf32r(r1[4]));
        }
    }
    const float bz2_0 = b2[wid * 16 + gid];
    const float bz2_1 = b2[wid * 16 + 8 + gid];
    // ---- W3 fragments: all warps own 32 channels (2 m-tiles); K=128 ----
    uint32_t a3f[2][16][4];
    {
        int mb = wid * 32;
#pragma unroll
        for (int mt = 0; mt < 2; mt++)
#pragma unroll
            for (int ks = 0; ks < 16; ks++) {
                const float* wb = W3 + (size_t)(mb + mt * 16 + gid) * 128 + ks * 8 + tig;
                a3f[mt][ks][0] = __float_as_uint(tf32r(wb[0]));
                a3f[mt][ks][1] = __float_as_uint(tf32r(wb[8 * 128]));
                a3f[mt][ks][2] = __float_as_uint(tf32r(wb[4]));
                a3f[mt][ks][3] = __float_as_uint(tf32r(wb[8 * 128 + 4]));
            }
    }
    float bz3[2][2];
#pragma unroll
    for (int mt = 0; mt < 2; mt++) {
        bz3[mt][0] = b3[wid * 32 + mt * 16 + gid];
        bz3[mt][1] = b3[wid * 32 + mt * 16 + 8 + gid];
    }

    // chunk m covers ord = 8m..8m+7, ord = s*4 + b  ->  s <= 2m+1
    for (int m = cc; m < NCHUNK; m += NCONS) {
        const int need = 2 * m + 2;
        if (tid < BB) {
            while (g_progress[tid] < need) __nanosleep(128);
        }
        __syncthreads();
        __threadfence();                       // order data reads after poll

        // ---- ball query: warp w -> ord = 8m + w ----
        {
            int ordg = 8 * m + wid;
            int bq = ordg & 3, sq = ordg >> 2;
            int g  = bq * 2048 + sq;
            const float* xb = xyz + (size_t)bq * NN * 3;
            float nx = __ldcg(newxyz + (size_t)g * 3 + 0);
            float ny = __ldcg(newxyz + (size_t)g * 3 + 1);
            float nz = __ldcg(newxyz + (size_t)g * 3 + 2);
            if (lane == 0) {
                sctr[wid * 3 + 0] = nx; sctr[wid * 3 + 1] = ny;
                sctr[wid * 3 + 2] = nz;
            }
            float nsq = __fadd_rn(__fadd_rn(__fmul_rn(nx, nx), __fmul_rn(ny, ny)),
                                  __fmul_rn(nz, nz));
            int cnt = 0, first = 0;
            int* gdst = sgi + wid * 32;
            for (int base = 0; base < NN; base += 32) {
                int p = base + lane;
                float x = xb[p * 3 + 0];
                float y = xb[p * 3 + 1];
                float z = xb[p * 3 + 2];
                float xsq = __fadd_rn(__fadd_rn(__fmul_rn(x, x), __fmul_rn(y, y)),
                                      __fmul_rn(z, z));
                float dot = __fmaf_rn(nz, z, __fmaf_rn(ny, y, __fmul_rn(nx, x)));
                float sq  = __fsub_rn(__fadd_rn(nsq, xsq), __fmul_rn(2.0f, dot));
                bool hit  = !(sq > 0.04f);
                unsigned hm = __ballot_sync(0xffffffffu, hit);
                if (cnt == 0 && hm) first = base + __ffs(hm) - 1;
                int pos = cnt + __popc(hm & ((1u << lane) - 1u));
                if (hit && pos < KK) gdst[pos] = p;
                cnt += __popc(hm);
                if (cnt >= KK) break;
            }
            if (cnt < KK) {
                for (int k = cnt + lane; k < KK; k += 32) gdst[k] = first;
            }
        }
        __syncthreads();

        // ---- fused MLP for the 8 groups of this chunk ----
        for (int gg = 0; gg < 8; gg++) {
            int ordg = 8 * m + gg;
            int bg = ordg & 3, sg = ordg >> 2;
            int g  = bg * 2048 + sg;

            // gather h0 (tf32): rows 0-2 xyz diff, 3-66 features
            if (tid < 96) {
                int c = tid >> 5, k = tid & 31;
                float v = xyz[((size_t)bg * NN + sgi[gg * 32 + k]) * 3 + c]
                          - sctr[gg * 3 + c];
                h0s[c * 33 + k] = tf32r(v);
            }
            for (int t = tid; t < 512; t += 256) {
                int k = t >> 4, q = t & 15;
                const float4 v = *(const float4*)(features +
                        ((size_t)bg * NN + sgi[gg * 32 + k]) * DD + q * 4);
                float* dst = &h0s[(3 + 4 * q) * 33 + k];
                dst[0]  = tf32r(v.x);
                dst[33] = tf32r(v.y);
                dst[66] = tf32r(v.z);
                dst[99] = tf32r(v.w);
            }
            __syncthreads();

            // layer 1: 72 -> 64 (warps 0-3)
            if (wid < 4) {
                float d[4][4];
#pragma unroll
                for (int nt = 0; nt < 4; nt++) {
                    d[nt][0] = bz1_0; d[nt][1] = bz1_0;
                    d[nt][2] = bz1_1; d[nt][3] = bz1_1;
                }
#pragma unroll
                for (int ks = 0; ks < 9; ks++)
#pragma unroll
                    for (int nt = 0; nt < 4; nt++) {
                        uint32_t b0 = __float_as_uint(h0s[(ks * 8 + tig) * 33 + nt * 8 + gid]);
                        uint32_t b1v = __float_as_uint(h0s[(ks * 8 + tig + 4) * 33 + nt * 8 + gid]);
                        mma_tf32(d[nt][0], d[nt][1], d[nt][2], d[nt][3],
                                 a1f[ks][0], a1f[ks][1], a1f[ks][2], a1f[ks][3], b0, b1v);
                    }
                int mb = wid * 16;
#pragma unroll
                for (int nt = 0; nt < 4; nt++) {
                    h1s[(mb + gid) * 33 + nt * 8 + 2 * tig]         = tf32r(fmaxf(d[nt][0], 0.0f));
                    h1s[(mb + gid) * 33 + nt * 8 + 2 * tig + 1]     = tf32r(fmaxf(d[nt][1], 0.0f));
                    h1s[(mb + 8 + gid) * 33 + nt * 8 + 2 * tig]     = tf32r(fmaxf(d[nt][2], 0.0f));
                    h1s[(mb + 8 + gid) * 33 + nt * 8 + 2 * tig + 1] = tf32r(fmaxf(d[nt][3], 0.0f));
                }
            }
            __syncthreads();

            // layer 2: 64 -> 128 (all warps)
            {
                float d[4][4];
#pragma unroll
                for (int nt = 0; nt < 4; nt++) {
                    d[nt][0] = bz2_0; d[nt][1] = bz2_0;
                    d[nt][2] = bz2_1; d[nt][3] = bz2_1;
                }
#pragma unroll
                for (int ks = 0; ks < 8; ks++)
#pragma unroll
                    for (int nt = 0; nt < 4; nt++) {
                        uint32_t b0 = __float_as_uint(h1s[(ks * 8 + tig) * 33 + nt * 8 + gid]);
                        uint32_t b1v = __float_as_uint(h1s[(ks * 8 + tig + 4) * 33 + nt * 8 + gid]);
                        mma_tf32(d[nt][0], d[nt][1], d[nt][2], d[nt][3],
                                 a2f[ks][0], a2f[ks][1], a2f[ks][2], a2f[ks][3], b0, b1v);
                    }
                int mb = wid * 16;
#pragma unroll
                for (int nt = 0; nt < 4; nt++) {
                    h2s[(mb + gid) * 33 + nt * 8 + 2 * tig]         = tf32r(fmaxf(d[nt][0], 0.0f));
                    h2s[(mb + gid) * 33 + nt * 8 + 2 * tig + 1]     = tf32r(fmaxf(d[nt][1], 0.0f));
                    h2s[(mb + 8 + gid) * 33 + nt * 8 + 2 * tig]     = tf32r(fmaxf(d[nt][2], 0.0f));
                    h2s[(mb + 8 + gid) * 33 + nt * 8 + 2 * tig + 1] = tf32r(fmaxf(d[nt][3], 0.0f));
                }
            }
            __syncthreads();

            // layer 3: 128 -> 256 (all warps, 32 ch), relu + k-max epilogue
            {
                float d[2][4][4];
#pragma unroll
                for (int mt = 0; mt < 2; mt++)
#pragma unroll
                    for (int nt = 0; nt < 4; nt++) {
                        d[mt][nt][0] = bz3[mt][0]; d[mt][nt][1] = bz3[mt][0];
                        d[mt][nt][2] = bz3[mt][1]; d[mt][nt][3] = bz3[mt][1];
                    }
#pragma unroll
                for (int ks = 0; ks < 16; ks++)
#pragma unroll
                    for (int nt = 0; nt < 4; nt++) {
                        uint32_t b0 = __float_as_uint(h2s[(ks * 8 + tig) * 33 + nt * 8 + gid]);
                        uint32_t b1v = __float_as_uint(h2s[(ks * 8 + tig + 4) * 33 + nt * 8 + gid]);
#pragma unroll
                        for (int mt = 0; mt < 2; mt++)
                            mma_tf32(d[mt][nt][0], d[mt][nt][1], d[mt][nt][2], d[mt][nt][3],
                                     a3f[mt][ks][0], a3f[mt][ks][1], a3f[mt][ks][2], a3f[mt][ks][3],
                                     b0, b1v);
                    }
                int mb = wid * 32;
#pragma unroll
                for (int mt = 0; mt < 2; mt++) {
                    float v0 = 0.0f, v1 = 0.0f;    // relu floor
#pragma unroll
                    for (int nt = 0; nt < 4; nt++) {
                        v0 = fmaxf(v0, fmaxf(d[mt][nt][0], d[mt][nt][1]));
                        v1 = fmaxf(v1, fmaxf(d[mt][nt][2], d[mt][nt][3]));
                    }
#pragma unroll
                    for (int off = 1; off <= 2; off <<= 1) {
                        v0 = fmaxf(v0, __shfl_xor_sync(0xffffffffu, v0, off));
                        v1 = fmaxf(v1, __shfl_xor_sync(0xffffffffu, v1, off));
                    }
                    if (tig == 0) {
                        feats_out[(size_t)g * 256 + mb + mt * 16 + gid]     = v0;
                        feats_out[(size_t)g * 256 + mb + mt * 16 + 8 + gid] = v1;
                    }
                }
            }
        }
    }
}

// ------------------------------------------------------------------
extern "C" void kernel_launch(void* const* d_in, const int* in_sizes, int n_in,
                              void* d_out, int out_size)
{
    const float* xyz      = (const float*)d_in[0];
    const float* features = (const float*)d_in[1];
    const float* W1 = (const float*)d_in[2];
    const float* b1 = (const float*)d_in[3];
    const float* W2 = (const float*)d_in[4];
    const float* b2 = (const float*)d_in[5];
    const float* W3 = (const float*)d_in[6];
    const float* b3 = (const float*)d_in[7];

    float* out    = (float*)d_out;
    float* newxyz = out;                         // [B,S,3] = 24576 floats
    float* feats  = out + (size_t)BB * SS * 3;   // [B,S,256]

    const int smem_bytes = NN * (int)sizeof(float4);   // 131072
    cudaFuncSetAttribute(fused_kernel, cudaFuncAttributeMaxDynamicSharedMemorySize,
                         smem_bytes);

    init_kernel<<<1, 32>>>();
    fused_kernel<<<BB + NCONS, 256, smem_bytes>>>(
        xyz, features, W1, b1, W2, b2, W3, b3, newxyz, feats);
}